// round 15
// baseline (speedup 1.0000x reference)
#include <cuda_runtime.h>
#include <cstdint>

// Problem constants (shapes fixed by the dataset): B=8192, S=4096.
#define MAX_B   8192
#define THREADS 256
#define WARPS_PER_CTA 8
#define STAGE_F4 64            // float4s per stage (1KB/stream/warp)

#define LOG2E 1.4426950408889634f
#define LN2   0.6931471805599453f

__device__ float g_partial[MAX_B];
__device__ unsigned int g_done = 0;

__device__ __forceinline__ float ex2f(float x) {
    float y; asm("ex2.approx.ftz.f32 %0, %1;" : "=f"(y) : "f"(x)); return y;
}
__device__ __forceinline__ float lg2f(float x) {
    float y; asm("lg2.approx.ftz.f32 %0, %1;" : "=f"(y) : "f"(x)); return y;
}
__device__ __forceinline__ float rcpf(float x) {
    float y; asm("rcp.approx.ftz.f32 %0, %1;" : "=f"(y) : "f"(x)); return y;
}
__device__ __forceinline__ void cp_async16(uint32_t saddr, const void* gptr) {
    asm volatile("cp.async.cg.shared.global [%0], [%1], 16;"
                 :: "r"(saddr), "l"(gptr));
}
#define CP_COMMIT() asm volatile("cp.async.commit_group;" ::: "memory")
#define CP_WAIT(n)  asm volatile("cp.async.wait_group %0;" :: "n"(n) : "memory")

// Per-element focal term in log2 domain (missing the final *ln2 scale):
//   t   = d * log2e,  ep = 2^t,  u = 1 + ep
//   om  = sigmoid(d)      = ep / u
//   sp2 = softplus(d)/ln2 = lg2(u)
//   fl2 = om^2 * sp2      (true fl = fl2 * ln2)
// 3 MUFU total (ex2, rcp, lg2).
__device__ __forceinline__ float focal2(float t) {
    const float ep  = ex2f(t);
    const float u   = 1.0f + ep;
    const float om  = ep * rcpf(u);
    const float sp2 = lg2f(u);
    return om * om * sp2;
}

// One WARP per row; grid = B/8 CTAs -> 8192 warps = 8192 rows, single wave
// (148 SMs x 7 CTAs = 1036 >= 1024).
// Depth-2 cp.async.cg pipeline with 1KB-per-stream stages: each lane stages
// its own 2x16B of scores + 2x16B of mask per stage into private smem slots
// and reads back only its own bytes -> per-thread wait_group suffices, no
// __syncwarp. Larger stages = longer sequential DRAM bursts per stream
// (page locality) + 2KB/warp in flight, with R13's clean XOR slot indexing
// (R14's %STAGES arithmetic caused the regression there).
// mask values are exactly {0,1}; head/tail exclusion via a per-row correction
// on lane 0 instead of per-element compares.
__global__ void __launch_bounds__(THREADS, 7)
focal_fused_kernel(const float* __restrict__ scores,
                   const int* __restrict__ head,
                   const int* __restrict__ tail,
                   const int* __restrict__ mask,
                   float* __restrict__ out,
                   int S, int B)
{
    __shared__ float4 sbuf[WARPS_PER_CTA][2][STAGE_F4];
    __shared__ int4   mbuf[WARPS_PER_CTA][2][STAGE_F4];

    const int tid = threadIdx.x;
    const int wid = tid >> 5;
    const int lid = tid & 31;
    const int row = blockIdx.x * WARPS_PER_CTA + wid;

    const float* __restrict__ srow = scores + (size_t)row * S;
    const int*   __restrict__ mrow = mask   + (size_t)row * S;
    const float4* __restrict__ srow4 = reinterpret_cast<const float4*>(srow);
    const int4*   __restrict__ mrow4 = reinterpret_cast<const int4*>(mrow);

    // Per-slot smem addresses for this lane's two 16B positions per stream.
    uint32_t sbA[2], sbB[2], mbA[2], mbB[2];
    #pragma unroll
    for (int k = 0; k < 2; ++k) {
        sbA[k] = (uint32_t)__cvta_generic_to_shared(&sbuf[wid][k][lid]);
        sbB[k] = (uint32_t)__cvta_generic_to_shared(&sbuf[wid][k][lid + 32]);
        mbA[k] = (uint32_t)__cvta_generic_to_shared(&mbuf[wid][k][lid]);
        mbB[k] = (uint32_t)__cvta_generic_to_shared(&mbuf[wid][k][lid + 32]);
    }

    const int hp = head[row];
    const int tp = tail[row];
    const float pos  = __ldg(srow + tp);
    const float pos2 = pos * LOG2E;

    float sum2 = 0.0f;
    int   cnt  = 0;

    // Lane 0 pre-subtracts the head/tail contributions that the mask-only
    // loop below will (wrongly) include.
    if (lid == 0) {
        const int m_tp = __ldg(mrow + tp);
        if (m_tp == 1) {
            // d = 0 exactly: om = 0.5, sp2 = 1 -> fl2 = 0.25
            sum2 -= 0.25f;
            cnt  -= 1;
        }
        if (hp != tp) {
            const int m_hp = __ldg(mrow + hp);
            if (m_hp == 1) {
                const float s = __ldg(srow + hp);
                const float t = fmaf(s, LOG2E, -pos2);
                sum2 -= focal2(t);
                cnt  -= 1;
            }
        }
    }

    const int n4      = S >> 2;          // float4s per row (1024)
    const int nstages = n4 / STAGE_F4;   // 16 stages

    // Prologue: stages 0 and 1 in flight (one commit group each).
    cp_async16(sbA[0], srow4 + lid);
    cp_async16(sbB[0], srow4 + lid + 32);
    cp_async16(mbA[0], mrow4 + lid);
    cp_async16(mbB[0], mrow4 + lid + 32);
    CP_COMMIT();
    cp_async16(sbA[1], srow4 + STAGE_F4 + lid);
    cp_async16(sbB[1], srow4 + STAGE_F4 + lid + 32);
    cp_async16(mbA[1], mrow4 + STAGE_F4 + lid);
    cp_async16(mbB[1], mrow4 + STAGE_F4 + lid + 32);
    CP_COMMIT();

    int cur = 0;
    for (int s = 0; s < nstages; ++s) {
        // Stage s must have landed: allow 1 pending (s+1) in steady state.
        if (s + 1 < nstages) { CP_WAIT(1); } else { CP_WAIT(0); }

        // Pull this lane's stage-s bytes out of smem first...
        const float4 sv0 = sbuf[wid][cur][lid];
        const int4   mv0 = mbuf[wid][cur][lid];
        const float4 sv1 = sbuf[wid][cur][lid + 32];
        const int4   mv1 = mbuf[wid][cur][lid + 32];

        // ...then recycle slot `cur` with stage s+2 so the async engine works
        // underneath the FMA/MUFU chain below.
        if (s + 2 < nstages) {
            const int base = (s + 2) * STAGE_F4;
            cp_async16(sbA[cur], srow4 + base + lid);
            cp_async16(sbB[cur], srow4 + base + lid + 32);
            cp_async16(mbA[cur], mrow4 + base + lid);
            cp_async16(mbB[cur], mrow4 + base + lid + 32);
            CP_COMMIT();
        }

        const float sarr[8] = { sv0.x, sv0.y, sv0.z, sv0.w,
                                sv1.x, sv1.y, sv1.z, sv1.w };
        const int   marr[8] = { mv0.x, mv0.y, mv0.z, mv0.w,
                                mv1.x, mv1.y, mv1.z, mv1.w };
        #pragma unroll
        for (int j = 0; j < 8; ++j) {
            const float t   = fmaf(sarr[j], LOG2E, -pos2);
            const float fl2 = focal2(t);
            // mask in {0,1}: build 0.0f/1.0f weight with one IMAD (no I2F)
            const float mf  = __int_as_float(marr[j] * 0x3f800000);
            sum2 = fmaf(fl2, mf, sum2);
            cnt += marr[j];
        }

        cur ^= 1;
    }

    // Warp-only deterministic reduction (fixed shuffle order).
    #pragma unroll
    for (int o = 16; o > 0; o >>= 1) {
        sum2 += __shfl_down_sync(0xffffffffu, sum2, o);
        cnt  += __shfl_down_sync(0xffffffffu, cnt, o);
    }
    if (lid == 0)
        g_partial[row] = (cnt > 0) ? sum2 / (float)cnt : 0.0f;

    // Completion protocol: last CTA reduces all B partials in fixed order.
    __shared__ bool is_last;
    __syncthreads();
    if (tid == 0) {
        __threadfence();
        const unsigned int old = atomicAdd(&g_done, 1u);
        is_last = (old == (unsigned int)(gridDim.x - 1));
    }
    __syncthreads();

    if (is_last) {
        float fsum = 0.0f;
        const int nb4 = B >> 2;
        for (int i = tid; i < nb4; i += THREADS) {
            const float4 v = reinterpret_cast<const float4*>(g_partial)[i];
            fsum += (v.x + v.y) + (v.z + v.w);
        }
        #pragma unroll
        for (int o = 16; o > 0; o >>= 1)
            fsum += __shfl_down_sync(0xffffffffu, fsum, o);
        __shared__ float fs[8];
        if (lid == 0) fs[wid] = fsum;
        __syncthreads();
        if (wid == 0) {
            fsum = (lid < 8) ? fs[lid] : 0.0f;
            #pragma unroll
            for (int o = 4; o > 0; o >>= 1)
                fsum += __shfl_down_sync(0xffffffffu, fsum, o);
            if (lid == 0) {
                out[0] = fsum * (LN2 / (float)B);   // fold ln2 scale here
                g_done = 0;                          // reset for graph replay
            }
        }
    }
}

extern "C" void kernel_launch(void* const* d_in, const int* in_sizes, int n_in,
                              void* d_out, int out_size)
{
    // metadata order: scores [B,S] f32, head [B] i32, tail [B] i32, mask [B,S] i32
    const float* scores = (const float*)d_in[0];
    const int*   head   = (const int*)d_in[1];
    const int*   tail   = (const int*)d_in[2];
    const int*   mask   = (const int*)d_in[3];
    float* out = (float*)d_out;

    const int B = in_sizes[1];
    const int S = in_sizes[0] / B;

    const int grid = B / WARPS_PER_CTA;   // 1024 CTAs, one warp per row
    focal_fused_kernel<<<grid, THREADS>>>(scores, head, tail, mask, out, S, B);
}

// round 16
// speedup vs baseline: 1.2005x; 1.2005x over previous
#include <cuda_runtime.h>
#include <cstdint>

// Problem constants (shapes fixed by the dataset): B=8192, S=4096.
#define MAX_B   8192
#define THREADS 256
#define WARPS_PER_CTA 8

#define LOG2E 1.4426950408889634f
#define LN2   0.6931471805599453f

__device__ float g_partial[MAX_B];
__device__ unsigned int g_done = 0;

__device__ __forceinline__ float ex2f(float x) {
    float y; asm("ex2.approx.ftz.f32 %0, %1;" : "=f"(y) : "f"(x)); return y;
}
__device__ __forceinline__ float lg2f(float x) {
    float y; asm("lg2.approx.ftz.f32 %0, %1;" : "=f"(y) : "f"(x)); return y;
}
__device__ __forceinline__ float rcpf(float x) {
    float y; asm("rcp.approx.ftz.f32 %0, %1;" : "=f"(y) : "f"(x)); return y;
}
__device__ __forceinline__ void cp_async16(uint32_t saddr, const void* gptr) {
    asm volatile("cp.async.cg.shared.global [%0], [%1], 16;"
                 :: "r"(saddr), "l"(gptr));
}
#define CP_COMMIT() asm volatile("cp.async.commit_group;" ::: "memory")
#define CP_WAIT(n)  asm volatile("cp.async.wait_group %0;" :: "n"(n) : "memory")

// Per-element focal term in log2 domain (missing the final *ln2 scale):
//   t   = d * log2e,  ep = 2^t,  u = 1 + ep
//   om  = sigmoid(d)      = ep / u
//   sp2 = softplus(d)/ln2 = lg2(u)
//   fl2 = om^2 * sp2      (true fl = fl2 * ln2)
// 3 MUFU total (ex2, rcp, lg2).
__device__ __forceinline__ float focal2(float t) {
    const float ep  = ex2f(t);
    const float u   = 1.0f + ep;
    const float om  = ep * rcpf(u);
    const float sp2 = lg2f(u);
    return om * om * sp2;
}

// One WARP per row; grid = B/8 CTAs -> 8192 warps = 8192 rows, single wave.
// Streaming via cp.async.cg double-buffer (the R13 winner): each lane stages
// its own 16B of scores + 16B of mask per stage into a private smem slot and
// reads back only its own bytes -> per-thread wait_group suffices, no
// __syncwarp. The pipeline prologue is issued BEFORE the dependent pos/
// head/tail scalar loads so stages 0-1 stream underneath that ~1200cyc
// latency chain instead of behind it.
// mask values are exactly {0,1}; head/tail exclusion via a per-row correction
// on lane 0 instead of per-element compares.
__global__ void __launch_bounds__(THREADS, 8)
focal_fused_kernel(const float* __restrict__ scores,
                   const int* __restrict__ head,
                   const int* __restrict__ tail,
                   const int* __restrict__ mask,
                   float* __restrict__ out,
                   int S, int B)
{
    __shared__ float4 sbuf[WARPS_PER_CTA][2][32];
    __shared__ int4   mbuf[WARPS_PER_CTA][2][32];

    const int tid = threadIdx.x;
    const int wid = tid >> 5;
    const int lid = tid & 31;
    const int row = blockIdx.x * WARPS_PER_CTA + wid;

    const float* __restrict__ srow = scores + (size_t)row * S;
    const int*   __restrict__ mrow = mask   + (size_t)row * S;
    const float4* __restrict__ srow4 = reinterpret_cast<const float4*>(srow);
    const int4*   __restrict__ mrow4 = reinterpret_cast<const int4*>(mrow);

    const uint32_t sb0 = (uint32_t)__cvta_generic_to_shared(&sbuf[wid][0][lid]);
    const uint32_t sb1 = (uint32_t)__cvta_generic_to_shared(&sbuf[wid][1][lid]);
    const uint32_t mb0 = (uint32_t)__cvta_generic_to_shared(&mbuf[wid][0][lid]);
    const uint32_t mb1 = (uint32_t)__cvta_generic_to_shared(&mbuf[wid][1][lid]);

    // Prologue FIRST: stages 0 and 1 in flight before any dependent loads.
    cp_async16(sb0, srow4 + lid);
    cp_async16(mb0, mrow4 + lid);
    CP_COMMIT();
    cp_async16(sb1, srow4 + 32 + lid);
    cp_async16(mb1, mrow4 + 32 + lid);
    CP_COMMIT();

    const int hp = head[row];
    const int tp = tail[row];
    const float pos  = __ldg(srow + tp);
    const float pos2 = pos * LOG2E;

    float sum2 = 0.0f;
    int   cnt  = 0;

    // Lane 0 pre-subtracts the head/tail contributions that the mask-only
    // loop below will (wrongly) include. Runs while stages 0-1 stream.
    if (lid == 0) {
        const int m_tp = __ldg(mrow + tp);
        if (m_tp == 1) {
            // d = 0 exactly: om = 0.5, sp2 = 1 -> fl2 = 0.25
            sum2 -= 0.25f;
            cnt  -= 1;
        }
        if (hp != tp) {
            const int m_hp = __ldg(mrow + hp);
            if (m_hp == 1) {
                const float s = __ldg(srow + hp);
                const float t = fmaf(s, LOG2E, -pos2);
                sum2 -= focal2(t);
                cnt  -= 1;
            }
        }
    }

    const int n4      = S >> 2;      // float4s per row (1024)
    const int nstages = n4 >> 5;     // 32 stages of (32 float4 + 32 int4)

    for (int s = 0; s < nstages - 1; ++s) {
        const int cur = s & 1, nxt = cur ^ 1;
        // Issue stage s+1 (one group), then wait until only it is pending
        // -> stage s's bytes (this lane's own copies) have landed in smem.
        const int base = (s + 1) << 5;
        cp_async16(nxt ? sb1 : sb0, srow4 + base + lid);
        cp_async16(nxt ? mb1 : mb0, mrow4 + base + lid);
        CP_COMMIT();
        CP_WAIT(1);

        const float4 sv = sbuf[wid][cur][lid];
        const int4   mv = mbuf[wid][cur][lid];
        const float sarr[4] = { sv.x, sv.y, sv.z, sv.w };
        const int   marr[4] = { mv.x, mv.y, mv.z, mv.w };
        #pragma unroll
        for (int j = 0; j < 4; ++j) {
            const float t   = fmaf(sarr[j], LOG2E, -pos2);
            const float fl2 = focal2(t);
            // mask in {0,1}: build 0.0f/1.0f weight with one IMAD (no I2F)
            const float mf  = __int_as_float(marr[j] * 0x3f800000);
            sum2 = fmaf(fl2, mf, sum2);
            cnt += marr[j];
        }
    }

    // Epilogue: last stage.
    CP_WAIT(0);
    {
        const int cur = (nstages - 1) & 1;
        const float4 sv = sbuf[wid][cur][lid];
        const int4   mv = mbuf[wid][cur][lid];
        const float sarr[4] = { sv.x, sv.y, sv.z, sv.w };
        const int   marr[4] = { mv.x, mv.y, mv.z, mv.w };
        #pragma unroll
        for (int j = 0; j < 4; ++j) {
            const float t   = fmaf(sarr[j], LOG2E, -pos2);
            const float fl2 = focal2(t);
            const float mf  = __int_as_float(marr[j] * 0x3f800000);
            sum2 = fmaf(fl2, mf, sum2);
            cnt += marr[j];
        }
    }

    // Warp-only deterministic reduction (fixed shuffle order).
    #pragma unroll
    for (int o = 16; o > 0; o >>= 1) {
        sum2 += __shfl_down_sync(0xffffffffu, sum2, o);
        cnt  += __shfl_down_sync(0xffffffffu, cnt, o);
    }
    if (lid == 0)
        g_partial[row] = (cnt > 0) ? sum2 / (float)cnt : 0.0f;

    // Completion protocol: last CTA reduces all B partials in fixed order.
    __shared__ bool is_last;
    __syncthreads();
    if (tid == 0) {
        __threadfence();
        const unsigned int old = atomicAdd(&g_done, 1u);
        is_last = (old == (unsigned int)(gridDim.x - 1));
    }
    __syncthreads();

    if (is_last) {
        float fsum = 0.0f;
        const int nb4 = B >> 2;
        for (int i = tid; i < nb4; i += THREADS) {
            const float4 v = reinterpret_cast<const float4*>(g_partial)[i];
            fsum += (v.x + v.y) + (v.z + v.w);
        }
        #pragma unroll
        for (int o = 16; o > 0; o >>= 1)
            fsum += __shfl_down_sync(0xffffffffu, fsum, o);
        __shared__ float fs[8];
        if (lid == 0) fs[wid] = fsum;
        __syncthreads();
        if (wid == 0) {
            fsum = (lid < 8) ? fs[lid] : 0.0f;
            #pragma unroll
            for (int o = 4; o > 0; o >>= 1)
                fsum += __shfl_down_sync(0xffffffffu, fsum, o);
            if (lid == 0) {
                out[0] = fsum * (LN2 / (float)B);   // fold ln2 scale here
                g_done = 0;                          // reset for graph replay
            }
        }
    }
}

extern "C" void kernel_launch(void* const* d_in, const int* in_sizes, int n_in,
                              void* d_out, int out_size)
{
    // metadata order: scores [B,S] f32, head [B] i32, tail [B] i32, mask [B,S] i32
    const float* scores = (const float*)d_in[0];
    const int*   head   = (const int*)d_in[1];
    const int*   tail   = (const int*)d_in[2];
    const int*   mask   = (const int*)d_in[3];
    float* out = (float*)d_out;

    const int B = in_sizes[1];
    const int S = in_sizes[0] / B;

    const int grid = B / WARPS_PER_CTA;   // 1024 CTAs, one warp per row
    focal_fused_kernel<<<grid, THREADS>>>(scores, head, tail, mask, out, S, B);
}

// round 17
// speedup vs baseline: 1.2384x; 1.0316x over previous
#include <cuda_runtime.h>
#include <cstdint>

// Problem constants (shapes fixed by the dataset): B=8192, S=4096.
#define MAX_B   8192
#define THREADS 256
#define WARPS_PER_CTA 8
#define STAGES  3

#define LOG2E 1.4426950408889634f
#define LN2   0.6931471805599453f

__device__ float g_partial[MAX_B];
__device__ unsigned int g_done = 0;

__device__ __forceinline__ float ex2f(float x) {
    float y; asm("ex2.approx.ftz.f32 %0, %1;" : "=f"(y) : "f"(x)); return y;
}
__device__ __forceinline__ float lg2f(float x) {
    float y; asm("lg2.approx.ftz.f32 %0, %1;" : "=f"(y) : "f"(x)); return y;
}
__device__ __forceinline__ float rcpf(float x) {
    float y; asm("rcp.approx.ftz.f32 %0, %1;" : "=f"(y) : "f"(x)); return y;
}
__device__ __forceinline__ void cp_async16(uint32_t saddr, const void* gptr) {
    asm volatile("cp.async.cg.shared.global [%0], [%1], 16;"
                 :: "r"(saddr), "l"(gptr));
}
#define CP_COMMIT() asm volatile("cp.async.commit_group;" ::: "memory")
#define CP_WAIT(n)  asm volatile("cp.async.wait_group %0;" :: "n"(n) : "memory")

// Per-element focal term in log2 domain (missing the final *ln2 scale):
//   t   = d * log2e,  ep = 2^t,  u = 1 + ep
//   om  = sigmoid(d)      = ep / u
//   sp2 = softplus(d)/ln2 = lg2(u)
//   fl2 = om^2 * sp2      (true fl = fl2 * ln2)
// 3 MUFU total (ex2, rcp, lg2).
__device__ __forceinline__ float focal2(float t) {
    const float ep  = ex2f(t);
    const float u   = 1.0f + ep;
    const float om  = ep * rcpf(u);
    const float sp2 = lg2f(u);
    return om * om * sp2;
}

// One WARP per row; grid = B/8 CTAs -> 8192 warps = 8192 rows, single wave
// (148 SMs x 7 CTAs = 1036 >= 1024 CTAs).
// Depth-3 cp.async.cg pipeline, TWO groups pending per warp in steady state
// (2x the R13 in-flight coverage), with every smem slot index a compile-time
// literal via a 3x-unrolled steady loop -- the %STAGES indexing that sank R14
// is gone. Each lane stages its own 16B of scores + 16B of mask per stage
// into a private smem slot and reads back only its own bytes -> per-thread
// wait_group suffices, no __syncwarp.
// mask values are exactly {0,1}; head/tail exclusion via a per-row correction
// on lane 0 instead of per-element compares.
__global__ void __launch_bounds__(THREADS, 7)
focal_fused_kernel(const float* __restrict__ scores,
                   const int* __restrict__ head,
                   const int* __restrict__ tail,
                   const int* __restrict__ mask,
                   float* __restrict__ out,
                   int S, int B)
{
    __shared__ float4 sbuf[WARPS_PER_CTA][STAGES][32];
    __shared__ int4   mbuf[WARPS_PER_CTA][STAGES][32];

    const int tid = threadIdx.x;
    const int wid = tid >> 5;
    const int lid = tid & 31;
    const int row = blockIdx.x * WARPS_PER_CTA + wid;

    const float* __restrict__ srow = scores + (size_t)row * S;
    const int*   __restrict__ mrow = mask   + (size_t)row * S;
    const float4* __restrict__ srow4 = reinterpret_cast<const float4*>(srow);
    const int4*   __restrict__ mrow4 = reinterpret_cast<const int4*>(mrow);

    uint32_t sb[STAGES], mb[STAGES];
    #pragma unroll
    for (int k = 0; k < STAGES; ++k) {
        sb[k] = (uint32_t)__cvta_generic_to_shared(&sbuf[wid][k][lid]);
        mb[k] = (uint32_t)__cvta_generic_to_shared(&mbuf[wid][k][lid]);
    }

    const int hp = head[row];
    const int tp = tail[row];
    const float pos  = __ldg(srow + tp);
    const float pos2 = pos * LOG2E;

    float sum2 = 0.0f;
    int   cnt  = 0;

    // Lane 0 pre-subtracts the head/tail contributions that the mask-only
    // loop below will (wrongly) include.
    if (lid == 0) {
        const int m_tp = __ldg(mrow + tp);
        if (m_tp == 1) {
            // d = 0 exactly: om = 0.5, sp2 = 1 -> fl2 = 0.25
            sum2 -= 0.25f;
            cnt  -= 1;
        }
        if (hp != tp) {
            const int m_hp = __ldg(mrow + hp);
            if (m_hp == 1) {
                const float s = __ldg(srow + hp);
                const float t = fmaf(s, LOG2E, -pos2);
                sum2 -= focal2(t);
                cnt  -= 1;
            }
        }
    }

    // nstages = 32 stages of 32 float4 + 32 int4 per warp.
    // Steady stages 0..29 (10 blocks of 3, literal slot indices);
    // epilogue stages 30 (slot 0) and 31 (slot 1).

    // Consume helper: accumulate one stage's 4 elements for this lane.
    #define CONSUME(SLOT)                                                     \
    {                                                                         \
        const float4 sv = sbuf[wid][SLOT][lid];                               \
        const int4   mv = mbuf[wid][SLOT][lid];                               \
        const float sarr[4] = { sv.x, sv.y, sv.z, sv.w };                     \
        const int   marr[4] = { mv.x, mv.y, mv.z, mv.w };                     \
        _Pragma("unroll")                                                     \
        for (int j = 0; j < 4; ++j) {                                         \
            const float t   = fmaf(sarr[j], LOG2E, -pos2);                    \
            const float fl2 = focal2(t);                                      \
            const float mf  = __int_as_float(marr[j] * 0x3f800000);           \
            sum2 = fmaf(fl2, mf, sum2);                                       \
            cnt += marr[j];                                                   \
        }                                                                     \
    }

    // One steady step: issue stage s+2 into slot NXT, keep 2 groups pending,
    // consume stage s from slot CUR.
    #define STEP(CUR, NXT, S_IDX)                                             \
    {                                                                         \
        const int base = ((S_IDX) + 2) << 5;                                  \
        cp_async16(sb[NXT], srow4 + base + lid);                              \
        cp_async16(mb[NXT], mrow4 + base + lid);                              \
        CP_COMMIT();                                                          \
        CP_WAIT(2);                                                           \
        CONSUME(CUR);                                                         \
    }

    // Prologue: stages 0 and 1 in flight (one commit group each).
    cp_async16(sb[0], srow4 + lid);
    cp_async16(mb[0], mrow4 + lid);
    CP_COMMIT();
    cp_async16(sb[1], srow4 + 32 + lid);
    cp_async16(mb[1], mrow4 + 32 + lid);
    CP_COMMIT();

    #pragma unroll 1
    for (int blk = 0; blk < 10; ++blk) {
        const int s0 = blk * 3;
        STEP(0, 2, s0);        // stage s0   : cur slot 0, issue into slot 2
        STEP(1, 0, s0 + 1);    // stage s0+1 : cur slot 1, issue into slot 0
        STEP(2, 1, s0 + 2);    // stage s0+2 : cur slot 2, issue into slot 1
    }

    // Epilogue: stages 30 (slot 0) and 31 (slot 1), nothing left to issue.
    CP_WAIT(1);
    CONSUME(0);
    CP_WAIT(0);
    CONSUME(1);

    #undef STEP
    #undef CONSUME

    // Warp-only deterministic reduction (fixed shuffle order).
    #pragma unroll
    for (int o = 16; o > 0; o >>= 1) {
        sum2 += __shfl_down_sync(0xffffffffu, sum2, o);
        cnt  += __shfl_down_sync(0xffffffffu, cnt, o);
    }
    if (lid == 0)
        g_partial[row] = (cnt > 0) ? sum2 / (float)cnt : 0.0f;

    // Completion protocol: last CTA reduces all B partials in fixed order.
    __shared__ bool is_last;
    __syncthreads();
    if (tid == 0) {
        __threadfence();
        const unsigned int old = atomicAdd(&g_done, 1u);
        is_last = (old == (unsigned int)(gridDim.x - 1));
    }
    __syncthreads();

    if (is_last) {
        float fsum = 0.0f;
        const int nb4 = B >> 2;
        for (int i = tid; i < nb4; i += THREADS) {
            const float4 v = reinterpret_cast<const float4*>(g_partial)[i];
            fsum += (v.x + v.y) + (v.z + v.w);
        }
        #pragma unroll
        for (int o = 16; o > 0; o >>= 1)
            fsum += __shfl_down_sync(0xffffffffu, fsum, o);
        __shared__ float fs[8];
        if (lid == 0) fs[wid] = fsum;
        __syncthreads();
        if (wid == 0) {
            fsum = (lid < 8) ? fs[lid] : 0.0f;
            #pragma unroll
            for (int o = 4; o > 0; o >>= 1)
                fsum += __shfl_down_sync(0xffffffffu, fsum, o);
            if (lid == 0) {
                out[0] = fsum * (LN2 / (float)B);   // fold ln2 scale here
                g_done = 0;                          // reset for graph replay
            }
        }
    }
}

extern "C" void kernel_launch(void* const* d_in, const int* in_sizes, int n_in,
                              void* d_out, int out_size)
{
    // metadata order: scores [B,S] f32, head [B] i32, tail [B] i32, mask [B,S] i32
    const float* scores = (const float*)d_in[0];
    const int*   head   = (const int*)d_in[1];
    const int*   tail   = (const int*)d_in[2];
    const int*   mask   = (const int*)d_in[3];
    float* out = (float*)d_out;

    const int B = in_sizes[1];
    const int S = in_sizes[0] / B;

    const int grid = B / WARPS_PER_CTA;   // 1024 CTAs, one warp per row
    focal_fused_kernel<<<grid, THREADS>>>(scores, head, tail, mask, out, S, B);
}